// round 9
// baseline (speedup 1.0000x reference)
#include <cuda_runtime.h>
#include <cuda_bf16.h>
#include <cstdint>

#define BB 128
#define TT 4096
#define NN 32
#define FULL 0xffffffffu
#define KSEG 32                 // segments per chain
#define SEGLEN (TT / KSEG)      // 128
#define WARM 20                 // warm-up steps (Hilbert contraction burn-in)
#define WPB 8                   // warps per block in fb
#define NCHUNK 16
#define CHUNK (TT / NCHUNK)

// bf16 tapes for scaled forward/backward messages (scale cancels in ratios;
// bf16 quantization error averages out in the dice sums -> ~1e-4 output err).
__device__ __nv_bfloat16 g_a[(size_t)BB * TT * NN];
__device__ __nv_bfloat16 g_b[(size_t)BB * TT * NN];
__device__ float g_partial[BB][NCHUNK];

// Dual matvec step: two independent chains share the warp. Each chain's v is
// broadcast via smem; rows are read back as v2.u64 (f32x2-ready pairs, no
// packing movs) and combined with packed f32x2 FMAs against E2.
// Returns the two renormalized dots (scaled by rcp of element 0).
__device__ __forceinline__ float2 matvec_dual(float va, float vb,
                                              unsigned int sA, unsigned int sB,
                                              int lane,
                                              const unsigned long long* E2)
{
    asm volatile("st.shared.f32 [%0], %1;" :: "r"(sA + 4u * lane), "f"(va) : "memory");
    asm volatile("st.shared.f32 [%0], %1;" :: "r"(sB + 4u * lane), "f"(vb) : "memory");
    __syncwarp();

    unsigned long long aA0 = 0, aA1 = 0, aA2 = 0, aA3 = 0;
    unsigned long long aB0 = 0, aB1 = 0, aB2 = 0, aB3 = 0;
    float ra = 1.0f, rb = 1.0f;
    #pragma unroll
    for (int k = 0; k < 4; k++) {
        unsigned long long pa0, pa1, pa2, pa3, pb0, pb1, pb2, pb3;
        asm volatile("ld.shared.v2.u64 {%0,%1}, [%2];"
                     : "=l"(pa0), "=l"(pa1) : "r"(sA + 32u * k));
        asm volatile("ld.shared.v2.u64 {%0,%1}, [%2];"
                     : "=l"(pa2), "=l"(pa3) : "r"(sA + 32u * k + 16u));
        asm volatile("ld.shared.v2.u64 {%0,%1}, [%2];"
                     : "=l"(pb0), "=l"(pb1) : "r"(sB + 32u * k));
        asm volatile("ld.shared.v2.u64 {%0,%1}, [%2];"
                     : "=l"(pb2), "=l"(pb3) : "r"(sB + 32u * k + 16u));
        if (k == 0) {
            float v0a, v0b, d0, d1;
            asm("mov.b64 {%0,%1}, %2;" : "=f"(v0a), "=f"(d0) : "l"(pa0));
            asm("mov.b64 {%0,%1}, %2;" : "=f"(v0b), "=f"(d1) : "l"(pb0));
            ra = __frcp_rn(v0a);                  // renorm, off critical path
            rb = __frcp_rn(v0b);
        }
        asm("fma.rn.f32x2 %0, %1, %2, %0;" : "+l"(aA0) : "l"(pa0), "l"(E2[4 * k + 0]));
        asm("fma.rn.f32x2 %0, %1, %2, %0;" : "+l"(aB0) : "l"(pb0), "l"(E2[4 * k + 0]));
        asm("fma.rn.f32x2 %0, %1, %2, %0;" : "+l"(aA1) : "l"(pa1), "l"(E2[4 * k + 1]));
        asm("fma.rn.f32x2 %0, %1, %2, %0;" : "+l"(aB1) : "l"(pb1), "l"(E2[4 * k + 1]));
        asm("fma.rn.f32x2 %0, %1, %2, %0;" : "+l"(aA2) : "l"(pa2), "l"(E2[4 * k + 2]));
        asm("fma.rn.f32x2 %0, %1, %2, %0;" : "+l"(aB2) : "l"(pb2), "l"(E2[4 * k + 2]));
        asm("fma.rn.f32x2 %0, %1, %2, %0;" : "+l"(aA3) : "l"(pa3), "l"(E2[4 * k + 3]));
        asm("fma.rn.f32x2 %0, %1, %2, %0;" : "+l"(aB3) : "l"(pb3), "l"(E2[4 * k + 3]));
    }
    asm("add.rn.f32x2 %0, %0, %1;" : "+l"(aA0) : "l"(aA1));
    asm("add.rn.f32x2 %0, %0, %1;" : "+l"(aA2) : "l"(aA3));
    asm("add.rn.f32x2 %0, %0, %1;" : "+l"(aA0) : "l"(aA2));
    asm("add.rn.f32x2 %0, %0, %1;" : "+l"(aB0) : "l"(aB1));
    asm("add.rn.f32x2 %0, %0, %1;" : "+l"(aB2) : "l"(aB3));
    asm("add.rn.f32x2 %0, %0, %1;" : "+l"(aB0) : "l"(aB2));
    float la, ha, lb, hb;
    asm("mov.b64 {%0, %1}, %2;" : "=f"(la), "=f"(ha) : "l"(aA0));
    asm("mov.b64 {%0, %1}, %2;" : "=f"(lb), "=f"(hb) : "l"(aB0));
    return make_float2((la + ha) * ra, (lb + hb) * rb);
}

// ---------------------------------------------------------------------------
// Kernel 1: segmented fwd/bwd recursions, TWO segments per warp (j and j+16
// of the same batch+direction: identical E matrix, independent dependency
// chains -> 2x issue density at the same occupancy). Lane = state.
// Probability-domain recursion, per-step rescale (scale cancels in marginal
// ratios). Mid-chain segments start WARM steps early from a uniform vector;
// diag(P)E^T contracts direction error ~0.32x/step (Hilbert metric).
// Ragged clipping handled by clamped loads + predicated stores.
// ---------------------------------------------------------------------------
__global__ void __launch_bounds__(32 * WPB)
fb_kernel(const float* __restrict__ pots,
          const int*   __restrict__ lengths,
          const float* __restrict__ trans)
{
    __shared__ float buf[WPB][2][2][NN];

    const int lane = threadIdx.x & 31;
    const int w    = threadIdx.x >> 5;
    const int gw   = blockIdx.x * WPB + w;     // [0, 4096)
    const int b    = gw >> 5;
    const int rem  = gw & 31;
    const bool fwd = rem < 16;
    const int ps   = rem & 15;
    const int segA = ps, segB = ps + 16;

    const int len = lengths[b];
    const float* pot = pots + (size_t)b * TT * NN;

    const int t0A = segA * SEGLEN;
    const int t0B = segB * SEGLEN;
    if (t0A >= len) return;                    // then t0B >= len too
    const int t1A = (t0A + SEGLEN < len) ? t0A + SEGLEN : len;
    const int t1B = (t0B < len) ? ((t0B + SEGLEN < len) ? t0B + SEGLEN : len) : 0;

    // shared-space byte addresses of this warp's two ping-pong row pairs
    const unsigned int sbase =
        (unsigned int)__cvta_generic_to_shared(&buf[w][0][0][0]);
    // slot p: chain A row at sbase + p*256, chain B row at sbase + p*256 + 128

    unsigned long long E2[16];

    if (fwd) {
        #pragma unroll
        for (int k = 0; k < 16; k++) {
            float e0 = __expf(trans[(2 * k)     * NN + lane]);
            float e1 = __expf(trans[(2 * k + 1) * NN + lane]);
            asm("mov.b64 %0, {%1, %2};" : "=l"(E2[k]) : "f"(e0), "f"(e1));
        }
        __nv_bfloat16* A = g_a + (size_t)b * TT * NN;

        int tsA = t0A - WARM; if (tsA < 0) tsA = 0;
        int tsB = t0B - WARM;                  // t0B >= 2048, never clamps
        float aA = (tsA == 0) ? __expf(pot[lane]) : 1.0f;
        float aB = 1.0f;
        if (t0A == 0) A[lane] = __float2bfloat16(aA);

        int stepsA = t1A - 1 - tsA; if (stepsA < 0) stepsA = 0;
        int stepsB = t1B - 1 - tsB; if (stepsB < 0) stepsB = 0;
        const int nsteps = stepsA > stepsB ? stepsA : stepsB;

        int ta = tsA + 1, tb = tsB + 1;
        float prA = pot[(size_t)(ta <= TT - 1 ? ta : TT - 1) * NN + lane];
        float prB = pot[(size_t)(tb <= TT - 1 ? tb : TT - 1) * NN + lane];

        for (int k = 0; k < nsteps; ++k) {
            float Pa = __expf(prA);
            float Pb = __expf(prB);
            int na = ta + 1; if (na > TT - 1) na = TT - 1;
            int nb = tb + 1; if (nb > TT - 1) nb = TT - 1;
            prA = pot[(size_t)na * NN + lane];
            prB = pot[(size_t)nb * NN + lane];
            unsigned int sp = sbase + (unsigned int)(k & 1) * 256u;
            float2 s = matvec_dual(aA, aB, sp, sp + 128u, lane, E2);
            aA = s.x * Pa;
            aB = s.y * Pb;
            if (ta >= t0A && ta < t1A) A[(size_t)ta * NN + lane] = __float2bfloat16(aA);
            if (tb >= t0B && tb < t1B) A[(size_t)tb * NN + lane] = __float2bfloat16(aB);
            ++ta; ++tb;
        }
    } else {
        #pragma unroll
        for (int k = 0; k < 16; k++) {
            float e0 = __expf(trans[lane * NN + 2 * k]);
            float e1 = __expf(trans[lane * NN + 2 * k + 1]);
            asm("mov.b64 %0, {%1, %2};" : "=l"(E2[k]) : "f"(e0), "f"(e1));
        }
        __nv_bfloat16* Bv = g_b + (size_t)b * TT * NN;

        int tsA = t1A - 1 + WARM; if (tsA > len - 1) tsA = len - 1;
        int tsB = t1B - 1 + WARM; if (tsB > len - 1) tsB = len - 1;
        if (tsB < 0) tsB = 0;                   // inactive chain B
        float bA = 1.0f, bB = 1.0f;
        if (tsA < t1A) Bv[(size_t)tsA * NN + lane] = __float2bfloat16(1.0f);
        if (t1B > 0 && tsB < t1B) Bv[(size_t)tsB * NN + lane] = __float2bfloat16(1.0f);

        int stepsA = tsA - t0A; if (stepsA < 0) stepsA = 0;
        int stepsB = tsB - t0B; if (stepsB < 0) stepsB = 0;
        const int nsteps = stepsA > stepsB ? stepsA : stepsB;

        int ta = tsA, tb = tsB;
        float prA = pot[(size_t)ta * NN + lane];
        float prB = pot[(size_t)tb * NN + lane];

        for (int k = 0; k < nsteps; ++k) {
            float Pa = __expf(prA);
            float Pb = __expf(prB);
            int na = ta - 1; if (na < 0) na = 0;
            int nb = tb - 1; if (nb < 0) nb = 0;
            prA = pot[(size_t)na * NN + lane];
            prB = pot[(size_t)nb * NN + lane];
            unsigned int sp = sbase + (unsigned int)(k & 1) * 256u;
            float2 s = matvec_dual(bA * Pa, bB * Pb, sp, sp + 128u, lane, E2);
            bA = s.x;
            bB = s.y;
            if (ta - 1 >= t0A && ta - 1 < t1A) Bv[(size_t)(ta - 1) * NN + lane] = __float2bfloat16(bA);
            if (tb - 1 >= t0B && tb - 1 < t1B) Bv[(size_t)(tb - 1) * NN + lane] = __float2bfloat16(bB);
            --ta; --tb;
        }
    }
}

// ---------------------------------------------------------------------------
// Kernel 2: combine partials over bf16 tapes. grid (BB, NCHUNK).
// p_t(y_t) = a_y b_y / sum_k a_k b_k (per-t scales cancel).
// ---------------------------------------------------------------------------
__device__ __forceinline__ float2 bf2f(unsigned int u) {
    __nv_bfloat162 h = *reinterpret_cast<__nv_bfloat162*>(&u);
    return __bfloat1622float2(h);
}

__global__ void __launch_bounds__(256)
combine_kernel(const int* __restrict__ y_true,
               const int* __restrict__ lengths)
{
    const int b   = blockIdx.x;
    const int c   = blockIdx.y;
    const int tid = threadIdx.x;
    const int len = lengths[b];

    const int t_lo = c * CHUNK;
    int t_hi = t_lo + CHUNK; if (t_hi > len) t_hi = len;

    const __nv_bfloat16* Ab = g_a + (size_t)b * TT * NN;
    const __nv_bfloat16* Bb = g_b + (size_t)b * TT * NN;
    const int* Yb = y_true + (size_t)b * TT;

    float part = 0.f;
    for (int t = t_lo + tid; t < t_hi; t += 256) {
        const uint4* A4 = reinterpret_cast<const uint4*>(Ab + (size_t)t * NN);
        const uint4* B4 = reinterpret_cast<const uint4*>(Bb + (size_t)t * NN);
        int y = Yb[t];
        float s = 0.f, py = 0.f;
        #pragma unroll
        for (int q = 0; q < 4; q++) {
            uint4 ua = __ldcs(&A4[q]);
            uint4 ub = __ldcs(&B4[q]);
            unsigned int aw[4] = {ua.x, ua.y, ua.z, ua.w};
            unsigned int bw[4] = {ub.x, ub.y, ub.z, ub.w};
            #pragma unroll
            for (int i = 0; i < 4; i++) {
                float2 fa = bf2f(aw[i]);
                float2 fb = bf2f(bw[i]);
                s = fmaf(fa.x, fb.x, s);
                s = fmaf(fa.y, fb.y, s);
                if ((y >> 1) == q * 4 + i)
                    py = (y & 1) ? fa.y * fb.y : fa.x * fb.x;
            }
        }
        part += __fdividef(py, s);
    }

    #pragma unroll
    for (int off = 16; off > 0; off >>= 1)
        part += __shfl_down_sync(FULL, part, off);

    __shared__ float red[8];
    if ((tid & 31) == 0) red[tid >> 5] = part;
    __syncthreads();
    if (tid == 0) {
        float s = 0.f;
        #pragma unroll
        for (int w2 = 0; w2 < 8; w2++) s += red[w2];
        g_partial[b][c] = s;
    }
}

// ---------------------------------------------------------------------------
__global__ void finalize_kernel(const int* __restrict__ lengths,
                                float* __restrict__ out)
{
    const int b = threadIdx.x;
    if (b >= BB) return;
    float inter = 0.f;
    #pragma unroll
    for (int c = 0; c < NCHUNK; c++) inter += g_partial[b][c];
    float flen = (float)lengths[b];
    float dice = (2.0f * inter + 1.0f) / (2.0f * flen + 1.0f);
    out[b] = 1.0f - dice;
}

// ---------------------------------------------------------------------------
extern "C" void kernel_launch(void* const* d_in, const int* in_sizes, int n_in,
                              void* d_out, int out_size)
{
    const float* pots    = (const float*)d_in[0];   // [B,T,N] fp32
    const int*   y_true  = (const int*)  d_in[1];   // [B,T] int32
    const int*   lengths = (const int*)  d_in[2];   // [B] int32
    const float* trans   = (const float*)d_in[3];   // [N,N] fp32
    float* out = (float*)d_out;                     // [B] fp32

    fb_kernel<<<(2 * BB * KSEG) / (2 * WPB), 32 * WPB>>>(pots, lengths, trans);
    combine_kernel<<<dim3(BB, NCHUNK), 256>>>(y_true, lengths);
    finalize_kernel<<<1, 128>>>(lengths, out);
}

// round 10
// speedup vs baseline: 1.8423x; 1.8423x over previous
#include <cuda_runtime.h>
#include <cuda_bf16.h>
#include <cstdint>

#define BB 128
#define TT 4096
#define NN 32
#define FULL 0xffffffffu
#define KSEG 32                 // segments per chain
#define SEGLEN (TT / KSEG)      // 128
#define WARM 20                 // warm-up steps (Hilbert contraction burn-in)
#define WPB 8                   // warps per block in fb
#define NCHUNK 16
#define CHUNK (TT / NCHUNK)

// bf16 tapes for scaled forward/backward messages (scale cancels in ratios).
__device__ __nv_bfloat16 g_a[(size_t)BB * TT * NN];
__device__ __nv_bfloat16 g_b[(size_t)BB * TT * NN];
__device__ float g_partial[BB][NCHUNK];

__device__ __forceinline__ __nv_bfloat162 asbf2(unsigned int u) {
    __nv_bfloat162 h;
    *reinterpret_cast<unsigned int*>(&h) = u;
    return h;
}

// Matvec step in bf16: broadcast v via a 64B smem row (STS.16), read back as
// 4x LDS.128 (16 bf16x2 operands, no packing movs), 16 HFMA2 against the
// bf16x2-packed E, 4-deep bf16 accumulators folded in fp32.
// Returns the renormalized dot (scaled by rcp of element 0), all lanes.
__device__ __forceinline__ float matvec_bf16(float v, unsigned int srow,
                                             int lane,
                                             const __nv_bfloat162* E2)
{
    __nv_bfloat16 vb = __float2bfloat16(v);
    unsigned short vs = *reinterpret_cast<unsigned short*>(&vb);
    asm volatile("st.shared.u16 [%0], %1;"
                 :: "r"(srow + 2u * (unsigned)lane), "h"(vs) : "memory");
    __syncwarp();
    unsigned int w0, w1, w2, w3, w4, w5, w6, w7, w8, w9, wa, wb, wc, wd, we, wf;
    asm volatile("ld.shared.v4.u32 {%0,%1,%2,%3}, [%4];"
                 : "=r"(w0), "=r"(w1), "=r"(w2), "=r"(w3) : "r"(srow));
    asm volatile("ld.shared.v4.u32 {%0,%1,%2,%3}, [%4];"
                 : "=r"(w4), "=r"(w5), "=r"(w6), "=r"(w7) : "r"(srow + 16u));
    asm volatile("ld.shared.v4.u32 {%0,%1,%2,%3}, [%4];"
                 : "=r"(w8), "=r"(w9), "=r"(wa), "=r"(wb) : "r"(srow + 32u));
    asm volatile("ld.shared.v4.u32 {%0,%1,%2,%3}, [%4];"
                 : "=r"(wc), "=r"(wd), "=r"(we), "=r"(wf) : "r"(srow + 48u));

    float r = __frcp_rn(__low2float(asbf2(w0)));      // renorm, off critical path

    __nv_bfloat162 z = __floats2bfloat162_rn(0.f, 0.f);
    __nv_bfloat162 acc0 = z, acc1 = z, acc2 = z, acc3 = z;
    acc0 = __hfma2(asbf2(w0), E2[0],  acc0);
    acc1 = __hfma2(asbf2(w1), E2[1],  acc1);
    acc2 = __hfma2(asbf2(w2), E2[2],  acc2);
    acc3 = __hfma2(asbf2(w3), E2[3],  acc3);
    acc0 = __hfma2(asbf2(w4), E2[4],  acc0);
    acc1 = __hfma2(asbf2(w5), E2[5],  acc1);
    acc2 = __hfma2(asbf2(w6), E2[6],  acc2);
    acc3 = __hfma2(asbf2(w7), E2[7],  acc3);
    acc0 = __hfma2(asbf2(w8), E2[8],  acc0);
    acc1 = __hfma2(asbf2(w9), E2[9],  acc1);
    acc2 = __hfma2(asbf2(wa), E2[10], acc2);
    acc3 = __hfma2(asbf2(wb), E2[11], acc3);
    acc0 = __hfma2(asbf2(wc), E2[12], acc0);
    acc1 = __hfma2(asbf2(wd), E2[13], acc1);
    acc2 = __hfma2(asbf2(we), E2[14], acc2);
    acc3 = __hfma2(asbf2(wf), E2[15], acc3);

    float2 f0 = __bfloat1622float2(acc0);
    float2 f1 = __bfloat1622float2(acc1);
    float2 f2 = __bfloat1622float2(acc2);
    float2 f3 = __bfloat1622float2(acc3);
    float s = ((f0.x + f0.y) + (f1.x + f1.y)) + ((f2.x + f2.y) + (f3.x + f3.y));
    return s * r;
}

// ---------------------------------------------------------------------------
// Kernel 1: segmented forward/backward recursions, one warp per
// (batch, direction, segment); warps of a block share (batch, direction) so
// they finish together. Lane = state. Probability-domain recursion with
// per-step rescale (scale cancels in marginal ratios -> no log/lse).
// Mid-chain segments start WARM steps early from a uniform positive vector;
// diag(P)E^T contracts direction error ~0.32x/step (Hilbert metric)
// => ~1e-10 after 20 steps. Boundary segments use the exact init.
// ---------------------------------------------------------------------------
__global__ void __launch_bounds__(32 * WPB)
fb_kernel(const float* __restrict__ pots,
          const int*   __restrict__ lengths,
          const float* __restrict__ trans)
{
    __shared__ __align__(16) __nv_bfloat16 buf[WPB][NN];

    const int lane = threadIdx.x & 31;
    const int w    = threadIdx.x >> 5;
    const int bid  = blockIdx.x;               // [0, 1024)
    const int b    = bid >> 3;
    const int sub  = bid & 7;
    const bool fwd = (sub & 1) == 0;
    const int seg  = (sub >> 1) * WPB + w;

    const int len = lengths[b];
    const int t0  = seg * SEGLEN;
    if (t0 >= len) return;                     // segment beyond this chain
    int t1 = t0 + SEGLEN; if (t1 > len) t1 = len;

    const float* pot = pots + (size_t)b * TT * NN;
    const unsigned int srow =
        (unsigned int)__cvta_generic_to_shared(&buf[w][0]);

    __nv_bfloat162 E2[16];                     // packed exp(trans) pairs

    if (fwd) {
        // pair k packs exp(trans[2k][lane]), exp(trans[2k+1][lane])
        #pragma unroll
        for (int k = 0; k < 16; k++)
            E2[k] = __floats2bfloat162_rn(__expf(trans[(2 * k)     * NN + lane]),
                                          __expf(trans[(2 * k + 1) * NN + lane]));

        __nv_bfloat16* A = g_a + (size_t)b * TT * NN;

        int tstart = t0 - WARM; if (tstart < 0) tstart = 0;
        float a;
        if (tstart == 0) {
            a = __expf(pot[lane]);
            if (t0 == 0) A[lane] = __float2bfloat16(a);
        } else {
            a = 1.0f;
        }

        float pr = pot[(size_t)(tstart + 1) * NN + lane];
        int t = tstart + 1;

        // warm-up (no stores)
        for (; t < t0; ++t) {
            float P = __expf(pr);
            pr = pot[(size_t)(t + 1) * NN + lane];
            float s = matvec_bf16(a, srow, lane, E2);
            a = s * P;
        }
        // main (stores)
        for (; t < t1; ++t) {
            float P = __expf(pr);
            int tn = t + 1; if (tn > TT - 1) tn = TT - 1;
            pr = pot[(size_t)tn * NN + lane];
            float s = matvec_bf16(a, srow, lane, E2);
            a = s * P;
            A[(size_t)t * NN + lane] = __float2bfloat16(a);
        }
    } else {
        // pair k packs exp(trans[lane][2k]), exp(trans[lane][2k+1])
        #pragma unroll
        for (int k = 0; k < 16; k++)
            E2[k] = __floats2bfloat162_rn(__expf(trans[lane * NN + 2 * k]),
                                          __expf(trans[lane * NN + 2 * k + 1]));

        __nv_bfloat16* Bv = g_b + (size_t)b * TT * NN;

        int tstart = t1 - 1 + WARM; if (tstart > len - 1) tstart = len - 1;
        float bv = 1.0f;                       // exact at len-1
        if (tstart < t1) Bv[(size_t)tstart * NN + lane] = __float2bfloat16(1.0f);

        float pr = pot[(size_t)tstart * NN + lane];
        int t = tstart;

        // warm-up: produce b_{t-1} for t-1 >= t1 (no stores)
        for (; t > t1; --t) {
            float P = __expf(pr);
            pr = pot[(size_t)(t - 1) * NN + lane];
            bv = matvec_bf16(bv * P, srow, lane, E2);
        }
        // main: produce and store b_{t-1} for t-1 in [t0, t1)
        for (; t >= t0 + 1; --t) {
            float P = __expf(pr);
            int tn = t - 1; if (tn < 0) tn = 0;
            pr = pot[(size_t)tn * NN + lane];
            bv = matvec_bf16(bv * P, srow, lane, E2);
            Bv[(size_t)(t - 1) * NN + lane] = __float2bfloat16(bv);
        }
    }
}

// ---------------------------------------------------------------------------
// Kernel 2: combine partials over bf16 tapes. grid (BB, NCHUNK).
// p_t(y_t) = a_y b_y / sum_k a_k b_k (per-t scales cancel).
// ---------------------------------------------------------------------------
__device__ __forceinline__ float2 bf2f(unsigned int u) {
    __nv_bfloat162 h = asbf2(u);
    return __bfloat1622float2(h);
}

__global__ void __launch_bounds__(256)
combine_kernel(const int* __restrict__ y_true,
               const int* __restrict__ lengths)
{
    const int b   = blockIdx.x;
    const int c   = blockIdx.y;
    const int tid = threadIdx.x;
    const int len = lengths[b];

    const int t_lo = c * CHUNK;
    int t_hi = t_lo + CHUNK; if (t_hi > len) t_hi = len;

    const __nv_bfloat16* Ab = g_a + (size_t)b * TT * NN;
    const __nv_bfloat16* Bb = g_b + (size_t)b * TT * NN;
    const int* Yb = y_true + (size_t)b * TT;

    float part = 0.f;
    for (int t = t_lo + tid; t < t_hi; t += 256) {
        const uint4* A4 = reinterpret_cast<const uint4*>(Ab + (size_t)t * NN);
        const uint4* B4 = reinterpret_cast<const uint4*>(Bb + (size_t)t * NN);
        int y = Yb[t];
        float s = 0.f, py = 0.f;
        #pragma unroll
        for (int q = 0; q < 4; q++) {
            uint4 ua = __ldcs(&A4[q]);
            uint4 ub = __ldcs(&B4[q]);
            unsigned int aw[4] = {ua.x, ua.y, ua.z, ua.w};
            unsigned int bw[4] = {ub.x, ub.y, ub.z, ub.w};
            #pragma unroll
            for (int i = 0; i < 4; i++) {
                float2 fa = bf2f(aw[i]);
                float2 fb = bf2f(bw[i]);
                s = fmaf(fa.x, fb.x, s);
                s = fmaf(fa.y, fb.y, s);
                if ((y >> 1) == q * 4 + i)
                    py = (y & 1) ? fa.y * fb.y : fa.x * fb.x;
            }
        }
        part += __fdividef(py, s);
    }

    #pragma unroll
    for (int off = 16; off > 0; off >>= 1)
        part += __shfl_down_sync(FULL, part, off);

    __shared__ float red[8];
    if ((tid & 31) == 0) red[tid >> 5] = part;
    __syncthreads();
    if (tid == 0) {
        float s = 0.f;
        #pragma unroll
        for (int w2 = 0; w2 < 8; w2++) s += red[w2];
        g_partial[b][c] = s;
    }
}

// ---------------------------------------------------------------------------
__global__ void finalize_kernel(const int* __restrict__ lengths,
                                float* __restrict__ out)
{
    const int b = threadIdx.x;
    if (b >= BB) return;
    float inter = 0.f;
    #pragma unroll
    for (int c = 0; c < NCHUNK; c++) inter += g_partial[b][c];
    float flen = (float)lengths[b];
    float dice = (2.0f * inter + 1.0f) / (2.0f * flen + 1.0f);
    out[b] = 1.0f - dice;
}

// ---------------------------------------------------------------------------
extern "C" void kernel_launch(void* const* d_in, const int* in_sizes, int n_in,
                              void* d_out, int out_size)
{
    const float* pots    = (const float*)d_in[0];   // [B,T,N] fp32
    const int*   y_true  = (const int*)  d_in[1];   // [B,T] int32
    const int*   lengths = (const int*)  d_in[2];   // [B] int32
    const float* trans   = (const float*)d_in[3];   // [N,N] fp32
    float* out = (float*)d_out;                     // [B] fp32

    fb_kernel<<<(2 * BB * KSEG) / WPB, 32 * WPB>>>(pots, lengths, trans);
    combine_kernel<<<dim3(BB, NCHUNK), 256>>>(y_true, lengths);
    finalize_kernel<<<1, 128>>>(lengths, out);
}

// round 11
// speedup vs baseline: 2.1745x; 1.1803x over previous
#include <cuda_runtime.h>
#include <cuda_bf16.h>
#include <cstdint>

#define BB 128
#define TT 4096
#define NN 32
#define FULL 0xffffffffu
#define KSEG 32                 // segments per chain
#define SEGLEN (TT / KSEG)      // 128
#define WARM 20                 // warm-up steps (Hilbert contraction burn-in)
#define WPB 8                   // warps per block in fb
#define NCHUNK 16
#define CHUNK (TT / NCHUNK)

// bf16 tapes for scaled forward/backward messages (scale cancels in ratios).
__device__ __nv_bfloat16 g_a[(size_t)BB * TT * NN];
__device__ __nv_bfloat16 g_b[(size_t)BB * TT * NN];
__device__ float g_partial[BB][NCHUNK];

__device__ __forceinline__ __nv_bfloat162 asbf2(unsigned int u) {
    __nv_bfloat162 h;
    *reinterpret_cast<unsigned int*>(&h) = u;
    return h;
}

// Matvec step in bf16: broadcast v via a 64B smem row (STS.16), read back as
// 4x LDS.128 (16 bf16x2 operands), 16 HFMA2 against bf16x2-packed E, bf16
// tree reduction (3 HADD2), single cvt at the end.
// Returns the renormalized dot (scaled by rcp of element 0), all lanes.
__device__ __forceinline__ float matvec_bf16(float v, unsigned int srow,
                                             int lane,
                                             const __nv_bfloat162* E2)
{
    __nv_bfloat16 vb = __float2bfloat16(v);
    unsigned short vs = *reinterpret_cast<unsigned short*>(&vb);
    asm volatile("st.shared.u16 [%0], %1;"
                 :: "r"(srow + 2u * (unsigned)lane), "h"(vs) : "memory");
    __syncwarp();
    unsigned int w0, w1, w2, w3, w4, w5, w6, w7, w8, w9, wa, wb, wc, wd, we, wf;
    asm volatile("ld.shared.v4.u32 {%0,%1,%2,%3}, [%4];"
                 : "=r"(w0), "=r"(w1), "=r"(w2), "=r"(w3) : "r"(srow));
    asm volatile("ld.shared.v4.u32 {%0,%1,%2,%3}, [%4];"
                 : "=r"(w4), "=r"(w5), "=r"(w6), "=r"(w7) : "r"(srow + 16u));
    asm volatile("ld.shared.v4.u32 {%0,%1,%2,%3}, [%4];"
                 : "=r"(w8), "=r"(w9), "=r"(wa), "=r"(wb) : "r"(srow + 32u));
    asm volatile("ld.shared.v4.u32 {%0,%1,%2,%3}, [%4];"
                 : "=r"(wc), "=r"(wd), "=r"(we), "=r"(wf) : "r"(srow + 48u));

    float r = __frcp_rn(__low2float(asbf2(w0)));      // renorm, off critical path

    __nv_bfloat162 z = __floats2bfloat162_rn(0.f, 0.f);
    __nv_bfloat162 acc0 = z, acc1 = z, acc2 = z, acc3 = z;
    acc0 = __hfma2(asbf2(w0), E2[0],  acc0);
    acc1 = __hfma2(asbf2(w1), E2[1],  acc1);
    acc2 = __hfma2(asbf2(w2), E2[2],  acc2);
    acc3 = __hfma2(asbf2(w3), E2[3],  acc3);
    acc0 = __hfma2(asbf2(w4), E2[4],  acc0);
    acc1 = __hfma2(asbf2(w5), E2[5],  acc1);
    acc2 = __hfma2(asbf2(w6), E2[6],  acc2);
    acc3 = __hfma2(asbf2(w7), E2[7],  acc3);
    acc0 = __hfma2(asbf2(w8), E2[8],  acc0);
    acc1 = __hfma2(asbf2(w9), E2[9],  acc1);
    acc2 = __hfma2(asbf2(wa), E2[10], acc2);
    acc3 = __hfma2(asbf2(wb), E2[11], acc3);
    acc0 = __hfma2(asbf2(wc), E2[12], acc0);
    acc1 = __hfma2(asbf2(wd), E2[13], acc1);
    acc2 = __hfma2(asbf2(we), E2[14], acc2);
    acc3 = __hfma2(asbf2(wf), E2[15], acc3);

    __nv_bfloat162 tsum = __hadd2(__hadd2(acc0, acc1), __hadd2(acc2, acc3));
    float2 f = __bfloat1622float2(tsum);
    return (f.x + f.y) * r;
}

// ---------------------------------------------------------------------------
// Kernel 1: segmented forward/backward recursions, one warp per
// (batch, direction, segment); warps of a block share (batch, direction).
// Lane = state. Probability-domain recursion with per-step rescale (scale
// cancels in marginal ratios -> no log/lse). Mid-chain segments start WARM
// steps early from a uniform positive vector; diag(P)E^T contracts direction
// error ~0.35x/step (Hilbert metric). Hot loops use pure pointer bumps; the
// boundary-clamped final step is peeled out of the loop.
// ---------------------------------------------------------------------------
__global__ void __launch_bounds__(32 * WPB)
fb_kernel(const float* __restrict__ pots,
          const int*   __restrict__ lengths,
          const float* __restrict__ trans)
{
    __shared__ __align__(16) __nv_bfloat16 buf[WPB][NN];

    const int lane = threadIdx.x & 31;
    const int w    = threadIdx.x >> 5;
    const int bid  = blockIdx.x;               // [0, 1024)
    const int b    = bid >> 3;
    const int sub  = bid & 7;
    const bool fwd = (sub & 1) == 0;
    const int seg  = (sub >> 1) * WPB + w;

    const int len = lengths[b];
    const int t0  = seg * SEGLEN;
    if (t0 >= len) return;                     // segment beyond this chain
    int t1 = t0 + SEGLEN; if (t1 > len) t1 = len;

    const float* pot = pots + (size_t)b * TT * NN;
    const unsigned int srow =
        (unsigned int)__cvta_generic_to_shared(&buf[w][0]);

    __nv_bfloat162 E2[16];                     // packed exp(trans) pairs

    if (fwd) {
        // pair k packs exp(trans[2k][lane]), exp(trans[2k+1][lane])
        #pragma unroll
        for (int k = 0; k < 16; k++)
            E2[k] = __floats2bfloat162_rn(__expf(trans[(2 * k)     * NN + lane]),
                                          __expf(trans[(2 * k + 1) * NN + lane]));

        __nv_bfloat16* A = g_a + (size_t)b * TT * NN;

        int tstart = t0 - WARM; if (tstart < 0) tstart = 0;
        float a;
        if (tstart == 0) {
            a = __expf(pot[lane]);
            if (t0 == 0) A[lane] = __float2bfloat16(a);
        } else {
            a = 1.0f;
        }

        const int tmain = (t0 > tstart + 1) ? t0 : tstart + 1;  // first stored t
        const float* pp = pot + (size_t)(tstart + 1) * NN + lane;
        float pr = *pp;

        // warm-up: t in [tstart+1, t0), no stores (prefetch stays <= t0)
        for (int t = tstart + 1; t < t0; ++t) {
            float P = __expf(pr);
            pp += NN; pr = *pp;
            a = matvec_bf16(a, srow, lane, E2) * P;
        }
        // main: t in [tmain, t1-1) with prefetch (stays <= t1-1 <= TT-1)
        __nv_bfloat16* Ap = A + (size_t)tmain * NN + lane;
        for (int t = tmain; t < t1 - 1; ++t) {
            float P = __expf(pr);
            pp += NN; pr = *pp;
            a = matvec_bf16(a, srow, lane, E2) * P;
            *Ap = __float2bfloat16(a); Ap += NN;
        }
        // peeled final step t = t1-1 (no prefetch)
        if (t1 - 1 >= tmain) {
            float P = __expf(pr);
            a = matvec_bf16(a, srow, lane, E2) * P;
            *Ap = __float2bfloat16(a);
        }
    } else {
        // pair k packs exp(trans[lane][2k]), exp(trans[lane][2k+1])
        #pragma unroll
        for (int k = 0; k < 16; k++)
            E2[k] = __floats2bfloat162_rn(__expf(trans[lane * NN + 2 * k]),
                                          __expf(trans[lane * NN + 2 * k + 1]));

        __nv_bfloat16* Bv = g_b + (size_t)b * TT * NN;

        int tstart = t1 - 1 + WARM; if (tstart > len - 1) tstart = len - 1;
        float bv = 1.0f;                       // exact at len-1
        if (tstart < t1) Bv[(size_t)tstart * NN + lane] = __float2bfloat16(1.0f);

        const float* pp = pot + (size_t)tstart * NN + lane;
        float pr = *pp;
        int t = tstart;

        // warm-up: t in (t1, tstart], produce unstored b_{t-1} (prefetch >= t1-1 >= t0 >= 0)
        for (; t > t1; --t) {
            float P = __expf(pr);
            pp -= NN; pr = *pp;
            bv = matvec_bf16(bv * P, srow, lane, E2);
        }
        // main: t down to t0+2 with prefetch (prefetch reads >= t0+1 >= 1)
        __nv_bfloat16* Bp = Bv + (size_t)(t - 1) * NN + lane;
        for (; t >= t0 + 2; --t) {
            float P = __expf(pr);
            pp -= NN; pr = *pp;
            bv = matvec_bf16(bv * P, srow, lane, E2);
            *Bp = __float2bfloat16(bv); Bp -= NN;
        }
        // peeled final step t = t0+1 (no prefetch; avoids reading row t0-1)
        if (t == t0 + 1) {
            float P = __expf(pr);
            bv = matvec_bf16(bv * P, srow, lane, E2);
            *Bp = __float2bfloat16(bv);
        }
    }
}

// ---------------------------------------------------------------------------
// Kernel 2: combine partials over bf16 tapes. grid (BB, NCHUNK).
// p_t(y_t) = a_y b_y / sum_k a_k b_k (per-t scales cancel).
// ---------------------------------------------------------------------------
__device__ __forceinline__ float2 bf2f(unsigned int u) {
    __nv_bfloat162 h = asbf2(u);
    return __bfloat1622float2(h);
}

__global__ void __launch_bounds__(256)
combine_kernel(const int* __restrict__ y_true,
               const int* __restrict__ lengths)
{
    const int b   = blockIdx.x;
    const int c   = blockIdx.y;
    const int tid = threadIdx.x;
    const int len = lengths[b];

    const int t_lo = c * CHUNK;
    int t_hi = t_lo + CHUNK; if (t_hi > len) t_hi = len;

    const __nv_bfloat16* Ab = g_a + (size_t)b * TT * NN;
    const __nv_bfloat16* Bb = g_b + (size_t)b * TT * NN;
    const int* Yb = y_true + (size_t)b * TT;

    float part = 0.f;
    for (int t = t_lo + tid; t < t_hi; t += 256) {
        const uint4* A4 = reinterpret_cast<const uint4*>(Ab + (size_t)t * NN);
        const uint4* B4 = reinterpret_cast<const uint4*>(Bb + (size_t)t * NN);
        int y = Yb[t];
        float s = 0.f, py = 0.f;
        #pragma unroll
        for (int q = 0; q < 4; q++) {
            uint4 ua = __ldcs(&A4[q]);
            uint4 ub = __ldcs(&B4[q]);
            unsigned int aw[4] = {ua.x, ua.y, ua.z, ua.w};
            unsigned int bw[4] = {ub.x, ub.y, ub.z, ub.w};
            #pragma unroll
            for (int i = 0; i < 4; i++) {
                float2 fa = bf2f(aw[i]);
                float2 fb = bf2f(bw[i]);
                s = fmaf(fa.x, fb.x, s);
                s = fmaf(fa.y, fb.y, s);
                if ((y >> 1) == q * 4 + i)
                    py = (y & 1) ? fa.y * fb.y : fa.x * fb.x;
            }
        }
        part += __fdividef(py, s);
    }

    #pragma unroll
    for (int off = 16; off > 0; off >>= 1)
        part += __shfl_down_sync(FULL, part, off);

    __shared__ float red[8];
    if ((tid & 31) == 0) red[tid >> 5] = part;
    __syncthreads();
    if (tid == 0) {
        float s = 0.f;
        #pragma unroll
        for (int w2 = 0; w2 < 8; w2++) s += red[w2];
        g_partial[b][c] = s;
    }
}

// ---------------------------------------------------------------------------
__global__ void finalize_kernel(const int* __restrict__ lengths,
                                float* __restrict__ out)
{
    const int b = threadIdx.x;
    if (b >= BB) return;
    float inter = 0.f;
    #pragma unroll
    for (int c = 0; c < NCHUNK; c++) inter += g_partial[b][c];
    float flen = (float)lengths[b];
    float dice = (2.0f * inter + 1.0f) / (2.0f * flen + 1.0f);
    out[b] = 1.0f - dice;
}

// ---------------------------------------------------------------------------
extern "C" void kernel_launch(void* const* d_in, const int* in_sizes, int n_in,
                              void* d_out, int out_size)
{
    const float* pots    = (const float*)d_in[0];   // [B,T,N] fp32
    const int*   y_true  = (const int*)  d_in[1];   // [B,T] int32
    const int*   lengths = (const int*)  d_in[2];   // [B] int32
    const float* trans   = (const float*)d_in[3];   // [N,N] fp32
    float* out = (float*)d_out;                     // [B] fp32

    fb_kernel<<<(2 * BB * KSEG) / WPB, 32 * WPB>>>(pots, lengths, trans);
    combine_kernel<<<dim3(BB, NCHUNK), 256>>>(y_true, lengths);
    finalize_kernel<<<1, 128>>>(lengths, out);
}

// round 12
// speedup vs baseline: 2.3300x; 1.0715x over previous
#include <cuda_runtime.h>
#include <cuda_bf16.h>
#include <cstdint>

#define BB 128
#define TT 4096
#define NN 32
#define FULL 0xffffffffu
#define KSEG 32                 // segments per chain
#define SEGLEN (TT / KSEG)      // 128
#define WARM 12                 // warm-up steps (Hilbert contraction burn-in)
#define WPB 8                   // warps per block in fb
#define NWORK_MAX (2 * BB * KSEG)
#define NCHUNK 16
#define CHUNK (TT / NCHUNK)

// bf16 tapes for scaled forward/backward messages (scale cancels in ratios).
__device__ __nv_bfloat16 g_a[(size_t)BB * TT * NN];
__device__ __nv_bfloat16 g_b[(size_t)BB * TT * NN];
__device__ float g_partial[BB][NCHUNK];
__device__ int   g_work[NWORK_MAX];   // packed (b<<7)|(dir<<6)|seg
__device__ int   g_nwork;

__device__ __forceinline__ __nv_bfloat162 asbf2(unsigned int u) {
    __nv_bfloat162 h;
    *reinterpret_cast<unsigned int*>(&h) = u;
    return h;
}

// Matvec step, bf16 state end-to-end: broadcast v via STS.16 into a 64B smem
// row, read back as 4x LDS.128 (16 bf16x2 operands), 16 HFMA2 against the
// bf16x2-packed E, 3 HADD2 + 1 HADD tree. Returns the raw dot s (bf16); the
// renorm factor rcp(v0) is returned separately (fp32, computed off-path).
__device__ __forceinline__ __nv_bfloat16 matvec_bf16(__nv_bfloat16 v,
                                                     unsigned int srow,
                                                     int lane,
                                                     const __nv_bfloat162* E2,
                                                     float& rout)
{
    unsigned short vs;
    *reinterpret_cast<__nv_bfloat16*>(&vs) = v;
    asm volatile("st.shared.u16 [%0], %1;"
                 :: "r"(srow + 2u * (unsigned)lane), "h"(vs) : "memory");
    __syncwarp();
    unsigned int w0, w1, w2, w3, w4, w5, w6, w7, w8, w9, wa, wb, wc, wd, we, wf;
    asm volatile("ld.shared.v4.u32 {%0,%1,%2,%3}, [%4];"
                 : "=r"(w0), "=r"(w1), "=r"(w2), "=r"(w3) : "r"(srow));
    asm volatile("ld.shared.v4.u32 {%0,%1,%2,%3}, [%4];"
                 : "=r"(w4), "=r"(w5), "=r"(w6), "=r"(w7) : "r"(srow + 16u));
    asm volatile("ld.shared.v4.u32 {%0,%1,%2,%3}, [%4];"
                 : "=r"(w8), "=r"(w9), "=r"(wa), "=r"(wb) : "r"(srow + 32u));
    asm volatile("ld.shared.v4.u32 {%0,%1,%2,%3}, [%4];"
                 : "=r"(wc), "=r"(wd), "=r"(we), "=r"(wf) : "r"(srow + 48u));

    rout = __frcp_rn(__low2float(asbf2(w0)));     // renorm, off critical path

    __nv_bfloat162 z = __floats2bfloat162_rn(0.f, 0.f);
    __nv_bfloat162 acc0 = z, acc1 = z, acc2 = z, acc3 = z;
    acc0 = __hfma2(asbf2(w0), E2[0],  acc0);
    acc1 = __hfma2(asbf2(w1), E2[1],  acc1);
    acc2 = __hfma2(asbf2(w2), E2[2],  acc2);
    acc3 = __hfma2(asbf2(w3), E2[3],  acc3);
    acc0 = __hfma2(asbf2(w4), E2[4],  acc0);
    acc1 = __hfma2(asbf2(w5), E2[5],  acc1);
    acc2 = __hfma2(asbf2(w6), E2[6],  acc2);
    acc3 = __hfma2(asbf2(w7), E2[7],  acc3);
    acc0 = __hfma2(asbf2(w8), E2[8],  acc0);
    acc1 = __hfma2(asbf2(w9), E2[9],  acc1);
    acc2 = __hfma2(asbf2(wa), E2[10], acc2);
    acc3 = __hfma2(asbf2(wb), E2[11], acc3);
    acc0 = __hfma2(asbf2(wc), E2[12], acc0);
    acc1 = __hfma2(asbf2(wd), E2[13], acc1);
    acc2 = __hfma2(asbf2(we), E2[14], acc2);
    acc3 = __hfma2(asbf2(wf), E2[15], acc3);

    __nv_bfloat162 tsum = __hadd2(__hadd2(acc0, acc1), __hadd2(acc2, acc3));
    return __hadd(__low2bfloat16(tsum), __high2bfloat16(tsum));
}

// ---------------------------------------------------------------------------
// Kernel 0: build the dense work list of active (batch, dir, seg) entries so
// every fb warp is live (dead segments would otherwise strand SMSP slots).
// ---------------------------------------------------------------------------
__global__ void plan_kernel(const int* __restrict__ lengths)
{
    __shared__ int cnt[BB];
    const int b = threadIdx.x;
    const int len = lengths[b];
    const int nseg = (len + SEGLEN - 1) / SEGLEN;
    cnt[b] = 2 * nseg;
    __syncthreads();
    int off = 0;
    for (int i = 0; i < b; i++) off += cnt[i];
    for (int s = 0; s < nseg; s++) {
        g_work[off + 2 * s]     = (b << 7) | (0 << 6) | s;   // fwd
        g_work[off + 2 * s + 1] = (b << 7) | (1 << 6) | s;   // bwd
    }
    if (b == BB - 1) g_nwork = off + 2 * nseg;
}

// ---------------------------------------------------------------------------
// Kernel 1: segmented forward/backward recursions over the compacted work
// list; one warp per entry, lane = state. Probability-domain recursion with
// per-step rescale (scale cancels in marginal ratios -> no log/lse).
// Mid-chain segments start WARM steps early from a uniform positive vector;
// diag(P)E^T contracts direction error ~0.32x/step (Hilbert metric)
// => ~1e-6 after 12 steps. Boundary segments use the exact init.
// State carried in bf16: the renorm*potential factor bf16(r*P) is computed
// off the critical path and applied with a single HMUL.
// ---------------------------------------------------------------------------
__global__ void __launch_bounds__(32 * WPB)
fb_kernel(const float* __restrict__ pots,
          const int*   __restrict__ lengths,
          const float* __restrict__ trans)
{
    __shared__ __align__(16) __nv_bfloat16 buf[WPB][NN];

    const int lane = threadIdx.x & 31;
    const int w    = threadIdx.x >> 5;
    const int gw   = blockIdx.x * WPB + w;
    if (gw >= g_nwork) return;
    const int e    = g_work[gw];
    const int b    = e >> 7;
    const bool fwd = ((e >> 6) & 1) == 0;
    const int seg  = e & 63;

    const int len = lengths[b];
    const int t0  = seg * SEGLEN;                // t0 < len guaranteed by plan
    int t1 = t0 + SEGLEN; if (t1 > len) t1 = len;

    const float* pot = pots + (size_t)b * TT * NN;
    const unsigned int srow =
        (unsigned int)__cvta_generic_to_shared(&buf[w][0]);

    __nv_bfloat162 E2[16];                       // packed exp(trans) pairs

    if (fwd) {
        // pair k packs exp(trans[2k][lane]), exp(trans[2k+1][lane])
        #pragma unroll
        for (int k = 0; k < 16; k++)
            E2[k] = __floats2bfloat162_rn(__expf(trans[(2 * k)     * NN + lane]),
                                          __expf(trans[(2 * k + 1) * NN + lane]));

        __nv_bfloat16* A = g_a + (size_t)b * TT * NN;

        int tstart = t0 - WARM; if (tstart < 0) tstart = 0;
        __nv_bfloat16 a;
        if (tstart == 0) {
            a = __float2bfloat16(__expf(pot[lane]));
            if (t0 == 0) A[lane] = a;
        } else {
            a = __float2bfloat16(1.0f);
        }

        const int tmain = (t0 > tstart + 1) ? t0 : tstart + 1;  // first stored t
        const float* pp = pot + (size_t)(tstart + 1) * NN + lane;
        float pr = *pp;
        float r;

        // warm-up: t in [tstart+1, t0), no stores
        for (int t = tstart + 1; t < t0; ++t) {
            float P = __expf(pr);
            pp += NN; pr = *pp;
            __nv_bfloat16 s = matvec_bf16(a, srow, lane, E2, r);
            a = __hmul(s, __float2bfloat16(r * P));
        }
        // main: t in [tmain, t1-1) with prefetch (stays <= t1-1 <= TT-1)
        __nv_bfloat16* Ap = A + (size_t)tmain * NN + lane;
        for (int t = tmain; t < t1 - 1; ++t) {
            float P = __expf(pr);
            pp += NN; pr = *pp;
            __nv_bfloat16 s = matvec_bf16(a, srow, lane, E2, r);
            a = __hmul(s, __float2bfloat16(r * P));
            *Ap = a; Ap += NN;
        }
        // peeled final step t = t1-1 (no prefetch)
        if (t1 - 1 >= tmain) {
            float P = __expf(pr);
            __nv_bfloat16 s = matvec_bf16(a, srow, lane, E2, r);
            a = __hmul(s, __float2bfloat16(r * P));
            *Ap = a;
        }
    } else {
        // pair k packs exp(trans[lane][2k]), exp(trans[lane][2k+1])
        #pragma unroll
        for (int k = 0; k < 16; k++)
            E2[k] = __floats2bfloat162_rn(__expf(trans[lane * NN + 2 * k]),
                                          __expf(trans[lane * NN + 2 * k + 1]));

        __nv_bfloat16* Bv = g_b + (size_t)b * TT * NN;

        int tstart = t1 - 1 + WARM; if (tstart > len - 1) tstart = len - 1;
        __nv_bfloat16 bv = __float2bfloat16(1.0f);   // exact at len-1
        if (tstart < t1) Bv[(size_t)tstart * NN + lane] = bv;

        const float* pp = pot + (size_t)tstart * NN + lane;
        float pr = *pp;
        float r;
        int t = tstart;

        // warm-up: t in (t1, tstart], produce unstored b_{t-1}
        for (; t > t1; --t) {
            __nv_bfloat16 Pb = __float2bfloat16(__expf(pr));
            pp -= NN; pr = *pp;
            __nv_bfloat16 s = matvec_bf16(__hmul(bv, Pb), srow, lane, E2, r);
            bv = __hmul(s, __float2bfloat16(r));
        }
        // main: t down to t0+2 with prefetch (prefetch reads >= t0+1 >= 1)
        __nv_bfloat16* Bp = Bv + (size_t)(t - 1) * NN + lane;
        for (; t >= t0 + 2; --t) {
            __nv_bfloat16 Pb = __float2bfloat16(__expf(pr));
            pp -= NN; pr = *pp;
            __nv_bfloat16 s = matvec_bf16(__hmul(bv, Pb), srow, lane, E2, r);
            bv = __hmul(s, __float2bfloat16(r));
            *Bp = bv; Bp -= NN;
        }
        // peeled final step t = t0+1 (no prefetch; avoids reading row t0-1)
        if (t == t0 + 1) {
            __nv_bfloat16 Pb = __float2bfloat16(__expf(pr));
            __nv_bfloat16 s = matvec_bf16(__hmul(bv, Pb), srow, lane, E2, r);
            bv = __hmul(s, __float2bfloat16(r));
            *Bp = bv;
        }
    }
}

// ---------------------------------------------------------------------------
// Kernel 2: combine partials over bf16 tapes. grid (BB, NCHUNK).
// p_t(y_t) = a_y b_y / sum_k a_k b_k (per-t scales cancel).
// ---------------------------------------------------------------------------
__device__ __forceinline__ float2 bf2f(unsigned int u) {
    return __bfloat1622float2(asbf2(u));
}

__global__ void __launch_bounds__(256)
combine_kernel(const int* __restrict__ y_true,
               const int* __restrict__ lengths)
{
    const int b   = blockIdx.x;
    const int c   = blockIdx.y;
    const int tid = threadIdx.x;
    const int len = lengths[b];

    const int t_lo = c * CHUNK;
    int t_hi = t_lo + CHUNK; if (t_hi > len) t_hi = len;

    const __nv_bfloat16* Ab = g_a + (size_t)b * TT * NN;
    const __nv_bfloat16* Bb = g_b + (size_t)b * TT * NN;
    const int* Yb = y_true + (size_t)b * TT;

    float part = 0.f;
    for (int t = t_lo + tid; t < t_hi; t += 256) {
        const uint4* A4 = reinterpret_cast<const uint4*>(Ab + (size_t)t * NN);
        const uint4* B4 = reinterpret_cast<const uint4*>(Bb + (size_t)t * NN);
        int y = Yb[t];
        float s = 0.f, py = 0.f;
        #pragma unroll
        for (int q = 0; q < 4; q++) {
            uint4 ua = __ldcs(&A4[q]);
            uint4 ub = __ldcs(&B4[q]);
            unsigned int aw[4] = {ua.x, ua.y, ua.z, ua.w};
            unsigned int bw[4] = {ub.x, ub.y, ub.z, ub.w};
            #pragma unroll
            for (int i = 0; i < 4; i++) {
                float2 fa = bf2f(aw[i]);
                float2 fb = bf2f(bw[i]);
                s = fmaf(fa.x, fb.x, s);
                s = fmaf(fa.y, fb.y, s);
                if ((y >> 1) == q * 4 + i)
                    py = (y & 1) ? fa.y * fb.y : fa.x * fb.x;
            }
        }
        part += __fdividef(py, s);
    }

    #pragma unroll
    for (int off = 16; off > 0; off >>= 1)
        part += __shfl_down_sync(FULL, part, off);

    __shared__ float red[8];
    if ((tid & 31) == 0) red[tid >> 5] = part;
    __syncthreads();
    if (tid == 0) {
        float s = 0.f;
        #pragma unroll
        for (int w2 = 0; w2 < 8; w2++) s += red[w2];
        g_partial[b][c] = s;
    }
}

// ---------------------------------------------------------------------------
__global__ void finalize_kernel(const int* __restrict__ lengths,
                                float* __restrict__ out)
{
    const int b = threadIdx.x;
    if (b >= BB) return;
    float inter = 0.f;
    #pragma unroll
    for (int c = 0; c < NCHUNK; c++) inter += g_partial[b][c];
    float flen = (float)lengths[b];
    float dice = (2.0f * inter + 1.0f) / (2.0f * flen + 1.0f);
    out[b] = 1.0f - dice;
}

// ---------------------------------------------------------------------------
extern "C" void kernel_launch(void* const* d_in, const int* in_sizes, int n_in,
                              void* d_out, int out_size)
{
    const float* pots    = (const float*)d_in[0];   // [B,T,N] fp32
    const int*   y_true  = (const int*)  d_in[1];   // [B,T] int32
    const int*   lengths = (const int*)  d_in[2];   // [B] int32
    const float* trans   = (const float*)d_in[3];   // [N,N] fp32
    float* out = (float*)d_out;                     // [B] fp32

    plan_kernel<<<1, BB>>>(lengths);
    fb_kernel<<<NWORK_MAX / WPB, 32 * WPB>>>(pots, lengths, trans);
    combine_kernel<<<dim3(BB, NCHUNK), 256>>>(y_true, lengths);
    finalize_kernel<<<1, 128>>>(lengths, out);
}

// round 13
// speedup vs baseline: 2.3506x; 1.0089x over previous
#include <cuda_runtime.h>
#include <cuda_bf16.h>
#include <cstdint>

#define BB 128
#define TT 4096
#define NN 32
#define FULL 0xffffffffu
#define KSEG 32                 // segments per chain
#define SEGLEN (TT / KSEG)      // 128
#define WARM 8                  // warm-up steps (Hilbert contraction burn-in)
#define WPB 8                   // warps per block in fb
#define NWORK_MAX (2 * BB * KSEG)
#define NCHUNK 16
#define CHUNK (TT / NCHUNK)

// bf16 tapes for scaled forward/backward messages (scale cancels in ratios).
__device__ __nv_bfloat16 g_a[(size_t)BB * TT * NN];
__device__ __nv_bfloat16 g_b[(size_t)BB * TT * NN];
__device__ float g_partial[BB][NCHUNK];
__device__ int   g_arrive[BB];        // combine last-block-done counters
__device__ int   g_work[NWORK_MAX];   // packed (b<<7)|(dir<<6)|seg
__device__ int   g_nwork;

__device__ __forceinline__ __nv_bfloat162 asbf2(unsigned int u) {
    __nv_bfloat162 h;
    *reinterpret_cast<unsigned int*>(&h) = u;
    return h;
}

// Matvec step, bf16 state end-to-end: broadcast v via STS.16 into a 64B smem
// row, read back as 4x LDS.128 (16 bf16x2 operands), 16 HFMA2 against the
// bf16x2-packed E, 3 HADD2 + 1 HADD tree. Returns the raw dot s (bf16); the
// renorm factor rcp(v0) is returned separately (fp32, computed off-path).
__device__ __forceinline__ __nv_bfloat16 matvec_bf16(__nv_bfloat16 v,
                                                     unsigned int srow,
                                                     int lane,
                                                     const __nv_bfloat162* E2,
                                                     float& rout)
{
    unsigned short vs;
    *reinterpret_cast<__nv_bfloat16*>(&vs) = v;
    asm volatile("st.shared.u16 [%0], %1;"
                 :: "r"(srow + 2u * (unsigned)lane), "h"(vs) : "memory");
    __syncwarp();
    unsigned int w0, w1, w2, w3, w4, w5, w6, w7, w8, w9, wa, wb, wc, wd, we, wf;
    asm volatile("ld.shared.v4.u32 {%0,%1,%2,%3}, [%4];"
                 : "=r"(w0), "=r"(w1), "=r"(w2), "=r"(w3) : "r"(srow));
    asm volatile("ld.shared.v4.u32 {%0,%1,%2,%3}, [%4];"
                 : "=r"(w4), "=r"(w5), "=r"(w6), "=r"(w7) : "r"(srow + 16u));
    asm volatile("ld.shared.v4.u32 {%0,%1,%2,%3}, [%4];"
                 : "=r"(w8), "=r"(w9), "=r"(wa), "=r"(wb) : "r"(srow + 32u));
    asm volatile("ld.shared.v4.u32 {%0,%1,%2,%3}, [%4];"
                 : "=r"(wc), "=r"(wd), "=r"(we), "=r"(wf) : "r"(srow + 48u));

    rout = __frcp_rn(__low2float(asbf2(w0)));     // renorm, off critical path

    __nv_bfloat162 z = __floats2bfloat162_rn(0.f, 0.f);
    __nv_bfloat162 acc0 = z, acc1 = z, acc2 = z, acc3 = z;
    acc0 = __hfma2(asbf2(w0), E2[0],  acc0);
    acc1 = __hfma2(asbf2(w1), E2[1],  acc1);
    acc2 = __hfma2(asbf2(w2), E2[2],  acc2);
    acc3 = __hfma2(asbf2(w3), E2[3],  acc3);
    acc0 = __hfma2(asbf2(w4), E2[4],  acc0);
    acc1 = __hfma2(asbf2(w5), E2[5],  acc1);
    acc2 = __hfma2(asbf2(w6), E2[6],  acc2);
    acc3 = __hfma2(asbf2(w7), E2[7],  acc3);
    acc0 = __hfma2(asbf2(w8), E2[8],  acc0);
    acc1 = __hfma2(asbf2(w9), E2[9],  acc1);
    acc2 = __hfma2(asbf2(wa), E2[10], acc2);
    acc3 = __hfma2(asbf2(wb), E2[11], acc3);
    acc0 = __hfma2(asbf2(wc), E2[12], acc0);
    acc1 = __hfma2(asbf2(wd), E2[13], acc1);
    acc2 = __hfma2(asbf2(we), E2[14], acc2);
    acc3 = __hfma2(asbf2(wf), E2[15], acc3);

    __nv_bfloat162 tsum = __hadd2(__hadd2(acc0, acc1), __hadd2(acc2, acc3));
    return __hadd(__low2bfloat16(tsum), __high2bfloat16(tsum));
}

// ---------------------------------------------------------------------------
// Kernel 0: build the dense work list of active (batch, dir, seg) entries so
// every fb warp is live. Also resets the combine arrival counters (the graph
// replays this kernel every call, so state is clean each iteration).
// ---------------------------------------------------------------------------
__global__ void plan_kernel(const int* __restrict__ lengths)
{
    __shared__ int cnt[BB];
    const int b = threadIdx.x;
    g_arrive[b] = 0;
    const int len = lengths[b];
    const int nseg = (len + SEGLEN - 1) / SEGLEN;
    cnt[b] = 2 * nseg;
    __syncthreads();
    int off = 0;
    for (int i = 0; i < b; i++) off += cnt[i];
    for (int s = 0; s < nseg; s++) {
        g_work[off + 2 * s]     = (b << 7) | (0 << 6) | s;   // fwd
        g_work[off + 2 * s + 1] = (b << 7) | (1 << 6) | s;   // bwd
    }
    if (b == BB - 1) g_nwork = off + 2 * nseg;
}

// ---------------------------------------------------------------------------
// Kernel 1: segmented forward/backward recursions over the compacted work
// list; one warp per entry, lane = state. Probability-domain recursion with
// per-step rescale (scale cancels in marginal ratios -> no log/lse).
// Mid-chain segments start WARM steps early from a uniform positive vector;
// diag(P)E^T contracts direction error ~0.32x/step (Hilbert metric)
// => ~1e-4 after 8 steps (averages out in the dice sums). Boundary segments
// use the exact init. State carried in bf16; bf16(r*P) applied off-path.
// ---------------------------------------------------------------------------
__global__ void __launch_bounds__(32 * WPB)
fb_kernel(const float* __restrict__ pots,
          const int*   __restrict__ lengths,
          const float* __restrict__ trans)
{
    __shared__ __align__(16) __nv_bfloat16 buf[WPB][NN];

    const int lane = threadIdx.x & 31;
    const int w    = threadIdx.x >> 5;
    const int gw   = blockIdx.x * WPB + w;
    if (gw >= g_nwork) return;
    const int e    = g_work[gw];
    const int b    = e >> 7;
    const bool fwd = ((e >> 6) & 1) == 0;
    const int seg  = e & 63;

    const int len = lengths[b];
    const int t0  = seg * SEGLEN;                // t0 < len guaranteed by plan
    int t1 = t0 + SEGLEN; if (t1 > len) t1 = len;

    const float* pot = pots + (size_t)b * TT * NN;
    const unsigned int srow =
        (unsigned int)__cvta_generic_to_shared(&buf[w][0]);

    __nv_bfloat162 E2[16];                       // packed exp(trans) pairs

    if (fwd) {
        // pair k packs exp(trans[2k][lane]), exp(trans[2k+1][lane])
        #pragma unroll
        for (int k = 0; k < 16; k++)
            E2[k] = __floats2bfloat162_rn(__expf(trans[(2 * k)     * NN + lane]),
                                          __expf(trans[(2 * k + 1) * NN + lane]));

        __nv_bfloat16* A = g_a + (size_t)b * TT * NN;

        int tstart = t0 - WARM; if (tstart < 0) tstart = 0;
        __nv_bfloat16 a;
        if (tstart == 0) {
            a = __float2bfloat16(__expf(pot[lane]));
            if (t0 == 0) A[lane] = a;
        } else {
            a = __float2bfloat16(1.0f);
        }

        const int tmain = (t0 > tstart + 1) ? t0 : tstart + 1;  // first stored t
        const float* pp = pot + (size_t)(tstart + 1) * NN + lane;
        float pr = *pp;
        float r;

        // warm-up: t in [tstart+1, t0), no stores
        for (int t = tstart + 1; t < t0; ++t) {
            float P = __expf(pr);
            pp += NN; pr = *pp;
            __nv_bfloat16 s = matvec_bf16(a, srow, lane, E2, r);
            a = __hmul(s, __float2bfloat16(r * P));
        }
        // main: t in [tmain, t1-1) with prefetch (stays <= t1-1 <= TT-1)
        __nv_bfloat16* Ap = A + (size_t)tmain * NN + lane;
        for (int t = tmain; t < t1 - 1; ++t) {
            float P = __expf(pr);
            pp += NN; pr = *pp;
            __nv_bfloat16 s = matvec_bf16(a, srow, lane, E2, r);
            a = __hmul(s, __float2bfloat16(r * P));
            *Ap = a; Ap += NN;
        }
        // peeled final step t = t1-1 (no prefetch)
        if (t1 - 1 >= tmain) {
            float P = __expf(pr);
            __nv_bfloat16 s = matvec_bf16(a, srow, lane, E2, r);
            a = __hmul(s, __float2bfloat16(r * P));
            *Ap = a;
        }
    } else {
        // pair k packs exp(trans[lane][2k]), exp(trans[lane][2k+1])
        #pragma unroll
        for (int k = 0; k < 16; k++)
            E2[k] = __floats2bfloat162_rn(__expf(trans[lane * NN + 2 * k]),
                                          __expf(trans[lane * NN + 2 * k + 1]));

        __nv_bfloat16* Bv = g_b + (size_t)b * TT * NN;

        int tstart = t1 - 1 + WARM; if (tstart > len - 1) tstart = len - 1;
        __nv_bfloat16 bv = __float2bfloat16(1.0f);   // exact at len-1
        if (tstart < t1) Bv[(size_t)tstart * NN + lane] = bv;

        const float* pp = pot + (size_t)tstart * NN + lane;
        float pr = *pp;
        float r;
        int t = tstart;

        // warm-up: t in (t1, tstart], produce unstored b_{t-1}
        for (; t > t1; --t) {
            __nv_bfloat16 Pb = __float2bfloat16(__expf(pr));
            pp -= NN; pr = *pp;
            __nv_bfloat16 s = matvec_bf16(__hmul(bv, Pb), srow, lane, E2, r);
            bv = __hmul(s, __float2bfloat16(r));
        }
        // main: t down to t0+2 with prefetch (prefetch reads >= t0+1 >= 1)
        __nv_bfloat16* Bp = Bv + (size_t)(t - 1) * NN + lane;
        for (; t >= t0 + 2; --t) {
            __nv_bfloat16 Pb = __float2bfloat16(__expf(pr));
            pp -= NN; pr = *pp;
            __nv_bfloat16 s = matvec_bf16(__hmul(bv, Pb), srow, lane, E2, r);
            bv = __hmul(s, __float2bfloat16(r));
            *Bp = bv; Bp -= NN;
        }
        // peeled final step t = t0+1 (no prefetch; avoids reading row t0-1)
        if (t == t0 + 1) {
            __nv_bfloat16 Pb = __float2bfloat16(__expf(pr));
            __nv_bfloat16 s = matvec_bf16(__hmul(bv, Pb), srow, lane, E2, r);
            bv = __hmul(s, __float2bfloat16(r));
            *Bp = bv;
        }
    }
}

// ---------------------------------------------------------------------------
// Kernel 2: combine partials over bf16 tapes + fused finalize. grid
// (BB, NCHUNK); block (b,c) handles t in [c*CHUNK, (c+1)*CHUNK) ∩ [0,len),
// writes its partial slot, then the LAST block to arrive for batch b
// (atomic counter; fixed summation order -> deterministic) sums the NCHUNK
// partials and writes out[b].  p_t(y_t) = a_y b_y / sum_k a_k b_k.
// ---------------------------------------------------------------------------
__device__ __forceinline__ float2 bf2f(unsigned int u) {
    return __bfloat1622float2(asbf2(u));
}

__global__ void __launch_bounds__(256)
combine_kernel(const int* __restrict__ y_true,
               const int* __restrict__ lengths,
               float*     __restrict__ out)
{
    const int b   = blockIdx.x;
    const int c   = blockIdx.y;
    const int tid = threadIdx.x;
    const int len = lengths[b];

    const int t_lo = c * CHUNK;
    int t_hi = t_lo + CHUNK; if (t_hi > len) t_hi = len;

    const __nv_bfloat16* Ab = g_a + (size_t)b * TT * NN;
    const __nv_bfloat16* Bb = g_b + (size_t)b * TT * NN;
    const int* Yb = y_true + (size_t)b * TT;

    float part = 0.f;
    for (int t = t_lo + tid; t < t_hi; t += 256) {
        const uint4* A4 = reinterpret_cast<const uint4*>(Ab + (size_t)t * NN);
        const uint4* B4 = reinterpret_cast<const uint4*>(Bb + (size_t)t * NN);
        int y = Yb[t];
        float s = 0.f, py = 0.f;
        #pragma unroll
        for (int q = 0; q < 4; q++) {
            uint4 ua = __ldcs(&A4[q]);
            uint4 ub = __ldcs(&B4[q]);
            unsigned int aw[4] = {ua.x, ua.y, ua.z, ua.w};
            unsigned int bw[4] = {ub.x, ub.y, ub.z, ub.w};
            #pragma unroll
            for (int i = 0; i < 4; i++) {
                float2 fa = bf2f(aw[i]);
                float2 fb = bf2f(bw[i]);
                s = fmaf(fa.x, fb.x, s);
                s = fmaf(fa.y, fb.y, s);
                if ((y >> 1) == q * 4 + i)
                    py = (y & 1) ? fa.y * fb.y : fa.x * fb.x;
            }
        }
        part += __fdividef(py, s);
    }

    #pragma unroll
    for (int off = 16; off > 0; off >>= 1)
        part += __shfl_down_sync(FULL, part, off);

    __shared__ float red[8];
    __shared__ int last;
    if ((tid & 31) == 0) red[tid >> 5] = part;
    __syncthreads();
    if (tid == 0) {
        float s = 0.f;
        #pragma unroll
        for (int w2 = 0; w2 < 8; w2++) s += red[w2];
        g_partial[b][c] = s;
        __threadfence();
        int prev = atomicAdd(&g_arrive[b], 1);
        last = (prev == NCHUNK - 1) ? 1 : 0;
    }
    __syncthreads();
    if (last && tid == 0) {
        float inter = 0.f;
        #pragma unroll
        for (int cc = 0; cc < NCHUNK; cc++) inter += g_partial[b][cc];
        float flen = (float)len;
        float dice = (2.0f * inter + 1.0f) / (2.0f * flen + 1.0f);
        out[b] = 1.0f - dice;
    }
}

// ---------------------------------------------------------------------------
extern "C" void kernel_launch(void* const* d_in, const int* in_sizes, int n_in,
                              void* d_out, int out_size)
{
    const float* pots    = (const float*)d_in[0];   // [B,T,N] fp32
    const int*   y_true  = (const int*)  d_in[1];   // [B,T] int32
    const int*   lengths = (const int*)  d_in[2];   // [B] int32
    const float* trans   = (const float*)d_in[3];   // [N,N] fp32
    float* out = (float*)d_out;                     // [B] fp32

    plan_kernel<<<1, BB>>>(lengths);
    fb_kernel<<<NWORK_MAX / WPB, 32 * WPB>>>(pots, lengths, trans);
    combine_kernel<<<dim3(BB, NCHUNK), 256>>>(y_true, lengths, out);
}